// round 13
// baseline (speedup 1.0000x reference)
#include <cuda_runtime.h>

// BatchDelayProcessor: lag-D feedback delay line.
//   c_k = x_k + FB * c_{k-1}         (carry per chain, c_{-1} = 0)
//   out_k = (1-MIX) * x_k + MIX * c_{k-1}
// One thread owns one float2 chain (20 k-blocks).
//
// R12 probe: phased half-batches. Profiles show NOTHING saturated (DRAM 68%,
// issue 12%) — possible residual R/W-turnaround / latency exposure. Group
// reads into MLP=10 bursts followed by write bursts, with launch_bounds(512,1)
// so ptxas has register headroom to keep the batch live (earlier front-batch
// attempt reported regs=32 => it was silently re-interleaved).

#define D_SAMP   22050
#define T_LEN    441000
#define B_SZ     64
#define NBLK     20          // T_LEN / D_SAMP
#define HALF     10
#define FB       0.3f
#define MIXC     0.5f

#define HD       (D_SAMP / 2)            // 11025 float2 chains per batch row
#define NCHAINS  (B_SZ * HD)             // 705600

#define CTA_THREADS 512

__global__ __launch_bounds__(CTA_THREADS, 1) void delay_kernel(const float* __restrict__ x,
                                                               float* __restrict__ out) {
    int idx = blockIdx.x * CTA_THREADS + threadIdx.x;
    if (idx >= NCHAINS) return;

    int b = idx / HD;
    int j = (idx - b * HD) * 2;

    const char* xbase = (const char*)(x + (size_t)b * T_LEN + j);
    char*       obase = (char*)(out + (size_t)b * T_LEN + j);

    const size_t blk_stride = (size_t)D_SAMP * sizeof(float);  // 88200 B

    float2 c;
    c.x = 0.0f;
    c.y = 0.0f;

#pragma unroll
    for (int h = 0; h < 2; h++) {
        const size_t base = (size_t)(h * HALF) * blk_stride;

        // read burst: 10 independent loads in flight
        float2 xv[HALF];
#pragma unroll
        for (int k = 0; k < HALF; k++)
            xv[k] = *reinterpret_cast<const float2*>(xbase + base + (size_t)k * blk_stride);

        // compute + write burst
        float2 o[HALF];
#pragma unroll
        for (int k = 0; k < HALF; k++) {
            o[k].x = fmaf(c.x, MIXC, xv[k].x * (1.0f - MIXC));
            o[k].y = fmaf(c.y, MIXC, xv[k].y * (1.0f - MIXC));
            c.x = fmaf(c.x, FB, xv[k].x);
            c.y = fmaf(c.y, FB, xv[k].y);
        }
#pragma unroll
        for (int k = 0; k < HALF; k++)
            *reinterpret_cast<float2*>(obase + base + (size_t)k * blk_stride) = o[k];
    }
}

extern "C" void kernel_launch(void* const* d_in, const int* in_sizes, int n_in,
                              void* d_out, int out_size) {
    const float* x = (const float*)d_in[0];
    float* out = (float*)d_out;

    const int blocks = (NCHAINS + CTA_THREADS - 1) / CTA_THREADS;  // 1379
    delay_kernel<<<blocks, CTA_THREADS>>>(x, out);
}

// round 14
// speedup vs baseline: 1.0008x; 1.0008x over previous
#include <cuda_runtime.h>

// BatchDelayProcessor: lag-D feedback delay line.
//   c_k = x_k + FB * c_{k-1}         (carry per chain, c_{-1} = 0)
//   out_k = (1-MIX) * x_k + MIX * c_{k-1}
// Each (b, j) with j in [0, D) is an independent length-NBLK chain:
// one thread owns one float2 chain, fully unrolled over the 20 k-blocks.
//
// FINAL (R13): the session's best-measured kernel (R0 form, 39.36us,
// DRAM 69.0% / 5461 GB/s). Thirteen rounds established the roofline:
// steady-state graph-replay traffic is compulsory 226 MB/launch (113 MB
// input re-read — the output's dirty fill evicts x from the 126 MB L2 and
// every replacement-policy control (evict_last/evict_first policies, .cs,
// .wt) is inert at the default carveout — plus 113 MB writeback), and
// ~5.5-5.7 TB/s is the device ceiling for an interleaved 50/50 R/W stream
// (proven by the occupancy/MLP invariance: 41% occ @ MLP=10 == 82% occ @
// MLP=2). 226 MB / 5.7 TB/s ~= 39.4us. Width (smem-staged 128-bit),
// persistent single-wave grids, and read/write burst phasing all measured
// neutral or worse.

#define D_SAMP   22050
#define T_LEN    441000
#define B_SZ     64
#define NBLK     20          // T_LEN / D_SAMP
#define FB       0.3f
#define MIXC     0.5f

// float2 vectorization: D_SAMP % 2 == 0
#define HD       (D_SAMP / 2)                 // 11025 float2 chains per batch row
#define NCHAINS  ((long long)B_SZ * HD)       // 705600

__global__ __launch_bounds__(256) void delay_kernel(const float* __restrict__ x,
                                                    float* __restrict__ out) {
    long long idx = (long long)blockIdx.x * blockDim.x + threadIdx.x;
    if (idx >= NCHAINS) return;

    int b = (int)(idx / HD);
    int j = (int)(idx % HD) * 2;

    const char* xbase = (const char*)(x + (size_t)b * T_LEN + j);
    char*       obase = (char*)(out + (size_t)b * T_LEN + j);

    float2 c;
    c.x = 0.0f;
    c.y = 0.0f;

    const size_t blk_stride = (size_t)D_SAMP * sizeof(float);  // 88200 B

#pragma unroll
    for (int k = 0; k < NBLK; k++) {
        float2 xv = *reinterpret_cast<const float2*>(xbase + (size_t)k * blk_stride);
        float2 o;
        // out = x*(1-MIX) + c*MIX
        o.x = fmaf(c.x, MIXC, xv.x * (1.0f - MIXC));
        o.y = fmaf(c.y, MIXC, xv.y * (1.0f - MIXC));
        *reinterpret_cast<float2*>(obase + (size_t)k * blk_stride) = o;
        // c = x + FB*c
        c.x = fmaf(c.x, FB, xv.x);
        c.y = fmaf(c.y, FB, xv.y);
    }
}

extern "C" void kernel_launch(void* const* d_in, const int* in_sizes, int n_in,
                              void* d_out, int out_size) {
    const float* x = (const float*)d_in[0];
    float* out = (float*)d_out;

    const int threads = 256;
    const long long nthreads = NCHAINS;
    const int blocks = (int)((nthreads + threads - 1) / threads);
    delay_kernel<<<blocks, threads>>>(x, out);
}

// round 15
// speedup vs baseline: 1.0081x; 1.0073x over previous
#include <cuda_runtime.h>

// BatchDelayProcessor: lag-D feedback delay line.
//   c_k = x_k + FB * c_{k-1}         (carry per chain, c_{-1} = 0)
//   out_k = (1-MIX) * x_k + MIX * c_{k-1}
// Each (b, j) with j in [0, D) is an independent length-NBLK chain:
// one thread owns one float2 chain, fully unrolled over the 20 k-blocks.
//
// FINAL (R14): exact-fit launch. 705600 chains = 2450 CTAs x 288 threads
// (9 warps) — no tail, no bounds check, 63/64 warps per SM. Otherwise the
// session's best kernel unchanged.
//
// Roofline (validated over 14 rounds): steady-state graph-replay traffic is
// compulsory 226 MB/launch (113 MB input re-read — the output's dirty fill
// evicts x from the 126 MB L2; every replacement-policy control
// (evict_last/evict_first createpolicy, .cs, .wt) is inert at the default
// carveout — plus 113 MB writeback), at the ~5.5-5.7 TB/s device ceiling
// for an interleaved 50/50 R/W stream (occupancy/MLP-invariant:
// 41% occ @ MLP=10 == 82% occ @ MLP=2). 226 MB / 5.7 TB/s ~= 39.4 us.
// Ruled out: smem-staged 128-bit width (-47%), persistent single-wave
// grid (-9%), read/write burst phasing (neutral), block 256/512 (tied).

#define D_SAMP   22050
#define T_LEN    441000
#define B_SZ     64
#define NBLK     20          // T_LEN / D_SAMP
#define FB       0.3f
#define MIXC     0.5f

// float2 vectorization: D_SAMP % 2 == 0
#define HD       (D_SAMP / 2)            // 11025 float2 chains per batch row
#define NCHAINS  (B_SZ * HD)             // 705600 = 2450 * 288 exactly

#define CTA_THREADS 288                  // 9 warps; exact-fit grid
#define GRID_CTAS   (NCHAINS / CTA_THREADS)   // 2450

__global__ __launch_bounds__(CTA_THREADS) void delay_kernel(const float* __restrict__ x,
                                                            float* __restrict__ out) {
    int idx = blockIdx.x * CTA_THREADS + threadIdx.x;   // always < NCHAINS

    int b = idx / HD;
    int j = (idx - b * HD) * 2;

    const char* xbase = (const char*)(x + (size_t)b * T_LEN + j);
    char*       obase = (char*)(out + (size_t)b * T_LEN + j);

    float2 c;
    c.x = 0.0f;
    c.y = 0.0f;

    const size_t blk_stride = (size_t)D_SAMP * sizeof(float);  // 88200 B

#pragma unroll
    for (int k = 0; k < NBLK; k++) {
        float2 xv = *reinterpret_cast<const float2*>(xbase + (size_t)k * blk_stride);
        float2 o;
        // out = x*(1-MIX) + c*MIX
        o.x = fmaf(c.x, MIXC, xv.x * (1.0f - MIXC));
        o.y = fmaf(c.y, MIXC, xv.y * (1.0f - MIXC));
        *reinterpret_cast<float2*>(obase + (size_t)k * blk_stride) = o;
        // c = x + FB*c
        c.x = fmaf(c.x, FB, xv.x);
        c.y = fmaf(c.y, FB, xv.y);
    }
}

extern "C" void kernel_launch(void* const* d_in, const int* in_sizes, int n_in,
                              void* d_out, int out_size) {
    const float* x = (const float*)d_in[0];
    float* out = (float*)d_out;
    delay_kernel<<<GRID_CTAS, CTA_THREADS>>>(x, out);
}